// round 3
// baseline (speedup 1.0000x reference)
#include <cuda_runtime.h>
#include <cuda_bf16.h>

// Problem constants
#define Bx 8
#define Lx 256
#define Dx 256
#define BLD (Bx*Lx*Dx)   // 524288
#define BLL (Bx*Lx*Lx)   // 524288

typedef unsigned long long u64;

// Scratch (device globals — no allocation allowed)
__device__ float g_A[BLD];   // Q @ Wa^T
__device__ float g_Bm[BLD];  // Q @ Wb^T
__device__ float g_H[BLD];   // Q @ Wd^T
__device__ float g_W[BLL];   // softmax weights

// ---- packed f32x2 helpers (Blackwell) --------------------------------------
__device__ __forceinline__ u64 pack2(float lo, float hi) {
    u64 r; asm("mov.b64 %0,{%1,%2};" : "=l"(r) : "f"(lo), "f"(hi)); return r;
}
__device__ __forceinline__ void unpack2(u64 v, float& lo, float& hi) {
    asm("mov.b64 {%0,%1},%2;" : "=f"(lo), "=f"(hi) : "l"(v));
}
__device__ __forceinline__ u64 ffma2(u64 a, u64 b, u64 c) {
    u64 d; asm("fma.rn.f32x2 %0,%1,%2,%3;" : "=l"(d) : "l"(a), "l"(b), "l"(c)); return d;
}
__device__ __forceinline__ u64 fadd2(u64 a, u64 b) {
    u64 d; asm("add.rn.f32x2 %0,%1,%2;" : "=l"(d) : "l"(a), "l"(b)); return d;
}

// ---------------------------------------------------------------------------
// Kernel 1: projections. C[m,n] = sum_k X[m,k] * W[n,k]  (NT GEMM)
// M = 2048, N = 256, K = 256. blockIdx.z picks {Wa,Wb,Wd}.
// BM=64, BN=64, BK=16, 256 threads, 4x4 per thread, f32x2, double-buffered.
// X stored DUPLICATED in smem so the broadcast operand is a single LDS.64.
// ---------------------------------------------------------------------------
__global__ __launch_bounds__(256) void proj_kernel(
    const float* __restrict__ Q,
    const float* __restrict__ Wa,
    const float* __restrict__ Wb,
    const float* __restrict__ Wd)
{
    const float* W = (blockIdx.z == 0) ? Wa : (blockIdx.z == 1) ? Wb : Wd;
    float* Out     = (blockIdx.z == 0) ? g_A : (blockIdx.z == 1) ? g_Bm : g_H;

    __shared__ __align__(16) float Xs[2][16][130];  // [k][2*r] duplicated pairs
    __shared__ __align__(16) float Ws[2][16][66];   // [k][n]

    int tid = threadIdx.x;
    int m0 = blockIdx.x * 64;
    int n0 = blockIdx.y * 64;
    int ty = tid >> 4;    // 0..15 -> 4 rows
    int tx = tid & 15;    // 0..15 -> 4 cols

    int sr = tid >> 2;          // 0..63 staging row
    int sk = (tid & 3) * 4;     // 0,4,8,12 staging k

    const float* xgp = Q + (m0 + sr) * Dx + sk;
    const float* wgp = W + (n0 + sr) * Dx + sk;

    float4 xr = *(const float4*)xgp;
    float4 wr = *(const float4*)wgp;

    {
        float xc[4] = {xr.x, xr.y, xr.z, xr.w};
        float wc[4] = {wr.x, wr.y, wr.z, wr.w};
#pragma unroll
        for (int c = 0; c < 4; c++) {
            Xs[0][sk + c][sr * 2]     = xc[c];
            Xs[0][sk + c][sr * 2 + 1] = xc[c];
            Ws[0][sk + c][sr]         = wc[c];
        }
    }
    __syncthreads();

    u64 acc[4][2];
#pragma unroll
    for (int m = 0; m < 4; m++) { acc[m][0] = 0ull; acc[m][1] = 0ull; }

#pragma unroll 1
    for (int it = 0; it < 16; it++) {
        int buf = it & 1;
        if (it < 15) {
            xr = *(const float4*)(xgp + (it + 1) * 16);
            wr = *(const float4*)(wgp + (it + 1) * 16);
        }
#pragma unroll
        for (int kk = 0; kk < 16; kk++) {
            u64 w0 = *(const u64*)&Ws[buf][kk][tx * 4];
            u64 w1 = *(const u64*)&Ws[buf][kk][tx * 4 + 2];
#pragma unroll
            for (int m = 0; m < 4; m++) {
                u64 xv = *(const u64*)&Xs[buf][kk][(ty * 4 + m) * 2]; // (x,x)
                acc[m][0] = ffma2(xv, w0, acc[m][0]);
                acc[m][1] = ffma2(xv, w1, acc[m][1]);
            }
        }
        if (it < 15) {
            __syncthreads();
            int nb = buf ^ 1;
            float xc[4] = {xr.x, xr.y, xr.z, xr.w};
            float wc[4] = {wr.x, wr.y, wr.z, wr.w};
#pragma unroll
            for (int c = 0; c < 4; c++) {
                Xs[nb][sk + c][sr * 2]     = xc[c];
                Xs[nb][sk + c][sr * 2 + 1] = xc[c];
                Ws[nb][sk + c][sr]         = wc[c];
            }
            __syncthreads();
        }
    }

#pragma unroll
    for (int m = 0; m < 4; m++) {
        float o0, o1, o2, o3;
        unpack2(acc[m][0], o0, o1);
        unpack2(acc[m][1], o2, o3);
        *(float4*)(Out + (m0 + ty * 4 + m) * Dx + n0 + tx * 4) =
            make_float4(o0, o1, o2, o3);
    }
}

// ---------------------------------------------------------------------------
// Kernel 2: edge scores + mask + softmax -> g_W, plus tail conversion.
// Block = (b, 8 rows). 128 threads = 4 warps, 2 rows/warp. Lane jl owns
// j = gp*64 + jl*2 (+0/1). Bm staged transposed in 8-wide c chunks,
// double-buffered with register prefetch. A rows and w2 stored duplicated.
// ---------------------------------------------------------------------------
__device__ __forceinline__ void softmax_row(
    u64 acc[4], int b, int i, int jl,
    const int* __restrict__ dep, float* __restrict__ depout)
{
    const int* dr = dep + (b * Lx + i) * Lx;
    float T[8]; int mk[8];
    float mx = -1e30f;
#pragma unroll
    for (int gp = 0; gp < 4; gp++) {
        int j0 = gp * 64 + jl * 2;
        int2 m2 = *(const int2*)(dr + j0);
        float lo, hi; unpack2(acc[gp], lo, hi);
        mk[2 * gp]     = (m2.x > 0);
        mk[2 * gp + 1] = (m2.y > 0);
        T[2 * gp]     = mk[2 * gp]     ? lo : -100.0f;
        T[2 * gp + 1] = mk[2 * gp + 1] ? hi : -100.0f;
        mx = fmaxf(mx, fmaxf(T[2 * gp], T[2 * gp + 1]));
        if (depout) {
            float2 dv = make_float2((float)m2.x, (float)m2.y);
            *(float2*)(depout + (b * Lx + i) * Lx + j0) = dv;
        }
    }
#pragma unroll
    for (int off = 16; off > 0; off >>= 1)
        mx = fmaxf(mx, __shfl_xor_sync(0xffffffffu, mx, off));

    float E[8], sum = 0.f;
#pragma unroll
    for (int g = 0; g < 8; g++) { E[g] = expf(T[g] - mx); sum += E[g]; }
#pragma unroll
    for (int off = 16; off > 0; off >>= 1)
        sum += __shfl_xor_sync(0xffffffffu, sum, off);

    float inv = 1.0f / sum;
    float* wRow = g_W + (b * Lx + i) * Lx;
#pragma unroll
    for (int gp = 0; gp < 4; gp++) {
        float2 o;
        o.x = mk[2 * gp]     ? E[2 * gp]     * inv : 0.f;
        o.y = mk[2 * gp + 1] ? E[2 * gp + 1] * inv : 0.f;
        *(float2*)(wRow + gp * 64 + jl * 2) = o;
    }
}

__global__ __launch_bounds__(128) void edge_kernel(
    const int* __restrict__ dep,
    const float* __restrict__ w2,
    const int* __restrict__ wl,
    float* __restrict__ dst)   // out + BLD, or nullptr
{
    int b  = blockIdx.y;
    int i0 = blockIdx.x * 8;

    __shared__ __align__(16) float Ash2[8][512];     // duplicated pairs
    __shared__ __align__(16) float Bt[2][8][260];    // [cl][j]
    __shared__ __align__(16) float w2d[512];         // duplicated pairs

    int tid = threadIdx.x;

    // stage 8 A rows, duplicated
#pragma unroll
    for (int p = 0; p < 4; p++) {
        int e = tid * 4 + p * 512;
        int il = e >> 8, c = e & 255;
        float4 v = *(const float4*)(g_A + (b * Lx + i0 + il) * Dx + c);
        float vc[4] = {v.x, v.y, v.z, v.w};
#pragma unroll
        for (int q = 0; q < 4; q++) {
            Ash2[il][(c + q) * 2]     = vc[q];
            Ash2[il][(c + q) * 2 + 1] = vc[q];
        }
    }
    {
        float v0 = w2[tid], v1 = w2[tid + 128];
        w2d[tid * 2] = v0;  w2d[tid * 2 + 1] = v0;
        w2d[(tid + 128) * 2] = v1;  w2d[(tid + 128) * 2 + 1] = v1;
    }
    if (dst && blockIdx.x == 0 && blockIdx.y == 0 && tid < Bx)
        dst[tid] = (float)wl[tid];
    float* depout = dst ? dst + Bx : nullptr;

    const float* Bbase = g_Bm + b * Lx * Dx;
    int j0r = tid, j1r = tid + 128;

    // prefetch chunk 0 (cols 0..7 of rows j0r, j1r)
    float4 pa0 = *(const float4*)(Bbase + j0r * Dx + 0);
    float4 pa1 = *(const float4*)(Bbase + j0r * Dx + 4);
    float4 pb0 = *(const float4*)(Bbase + j1r * Dx + 0);
    float4 pb1 = *(const float4*)(Bbase + j1r * Dx + 4);
    {
        float a0c[4] = {pa0.x, pa0.y, pa0.z, pa0.w};
        float a1c[4] = {pa1.x, pa1.y, pa1.z, pa1.w};
        float b0c[4] = {pb0.x, pb0.y, pb0.z, pb0.w};
        float b1c[4] = {pb1.x, pb1.y, pb1.z, pb1.w};
#pragma unroll
        for (int c = 0; c < 4; c++) {
            Bt[0][c][j0r]     = a0c[c];
            Bt[0][c + 4][j0r] = a1c[c];
            Bt[0][c][j1r]     = b0c[c];
            Bt[0][c + 4][j1r] = b1c[c];
        }
    }
    __syncthreads();

    int w  = tid >> 5;   // 0..3
    int jl = tid & 31;
    int r0 = 2 * w, r1 = 2 * w + 1;

    u64 acc0[4], acc1[4];
#pragma unroll
    for (int gp = 0; gp < 4; gp++) { acc0[gp] = 0ull; acc1[gp] = 0ull; }

#pragma unroll 1
    for (int ch = 0; ch < 32; ch++) {
        int buf = ch & 1;
        if (ch < 31) {
            int c0 = (ch + 1) * 8;
            pa0 = *(const float4*)(Bbase + j0r * Dx + c0);
            pa1 = *(const float4*)(Bbase + j0r * Dx + c0 + 4);
            pb0 = *(const float4*)(Bbase + j1r * Dx + c0);
            pb1 = *(const float4*)(Bbase + j1r * Dx + c0 + 4);
        }
#pragma unroll
        for (int cl = 0; cl < 8; cl++) {
            int c = ch * 8 + cl;
            u64 a0p = *(const u64*)&Ash2[r0][c * 2];   // (a,a) broadcast
            u64 a1p = *(const u64*)&Ash2[r1][c * 2];
            u64 up  = *(const u64*)&w2d[c * 2];
#pragma unroll
            for (int gp = 0; gp < 4; gp++) {
                u64 bt = *(const u64*)&Bt[buf][cl][gp * 64 + jl * 2];
                u64 s0 = fadd2(a0p, bt);
                u64 s1 = fadd2(a1p, bt);
                float x, y;
                unpack2(s0, x, y);
                u64 rr0 = pack2(fmaxf(x, 0.f), fmaxf(y, 0.f));
                unpack2(s1, x, y);
                u64 rr1 = pack2(fmaxf(x, 0.f), fmaxf(y, 0.f));
                acc0[gp] = ffma2(rr0, up, acc0[gp]);
                acc1[gp] = ffma2(rr1, up, acc1[gp]);
            }
        }
        if (ch < 31) {
            __syncthreads();
            int nb = buf ^ 1;
            float a0c[4] = {pa0.x, pa0.y, pa0.z, pa0.w};
            float a1c[4] = {pa1.x, pa1.y, pa1.z, pa1.w};
            float b0c[4] = {pb0.x, pb0.y, pb0.z, pb0.w};
            float b1c[4] = {pb1.x, pb1.y, pb1.z, pb1.w};
#pragma unroll
            for (int c = 0; c < 4; c++) {
                Bt[nb][c][j0r]     = a0c[c];
                Bt[nb][c + 4][j0r] = a1c[c];
                Bt[nb][c][j1r]     = b0c[c];
                Bt[nb][c + 4][j1r] = b1c[c];
            }
            __syncthreads();
        }
    }

    softmax_row(acc0, b, i0 + r0, jl, dep, depout);
    softmax_row(acc1, b, i0 + r1, jl, dep, depout);
}

// ---------------------------------------------------------------------------
// Kernel 3: agg = w @ H per batch, out = relu(q + agg).  NN GEMM 256x256x256.
// BM=64, BN=64, BK=16, 256 threads, 4x4 per thread, double-buffered.
// W (broadcast operand) stored duplicated.
// ---------------------------------------------------------------------------
__global__ __launch_bounds__(256) void agg_kernel(
    const float* __restrict__ Q,
    float* __restrict__ out)
{
    int b  = blockIdx.z;
    int i0 = blockIdx.x * 64;
    int c0 = blockIdx.y * 64;

    __shared__ __align__(16) float Wt[2][16][130];  // [k][2*i] duplicated
    __shared__ __align__(16) float Hs[2][16][68];   // [k][c]

    int tid = threadIdx.x;
    int ty = tid >> 4;   // 0..15 -> 4 i-rows
    int tx = tid & 15;   // 0..15 -> 4 c-cols

    int sr = tid >> 2;          // 0..63
    int sk = (tid & 3) * 4;     // 0,4,8,12
    int hk = tid >> 4;          // 0..15
    int hc = (tid & 15) * 4;    // 0..60

    const float* wgp = g_W + b * Lx * Lx + (i0 + sr) * Lx + sk;
    const float* hgp = g_H + b * Lx * Dx + hk * Dx + c0 + hc;

    float4 wr = *(const float4*)wgp;
    float4 hr = *(const float4*)hgp;
    {
        float wc[4] = {wr.x, wr.y, wr.z, wr.w};
#pragma unroll
        for (int c = 0; c < 4; c++) {
            Wt[0][sk + c][sr * 2]     = wc[c];
            Wt[0][sk + c][sr * 2 + 1] = wc[c];
        }
        *(float4*)&Hs[0][hk][hc] = hr;
    }
    __syncthreads();

    u64 acc[4][2];
#pragma unroll
    for (int m = 0; m < 4; m++) { acc[m][0] = 0ull; acc[m][1] = 0ull; }

#pragma unroll 1
    for (int it = 0; it < 16; it++) {
        int buf = it & 1;
        if (it < 15) {
            wr = *(const float4*)(wgp + (it + 1) * 16);
            hr = *(const float4*)(hgp + (it + 1) * 16 * Dx);
        }
#pragma unroll
        for (int kk = 0; kk < 16; kk++) {
            u64 h0 = *(const u64*)&Hs[buf][kk][tx * 4];
            u64 h1 = *(const u64*)&Hs[buf][kk][tx * 4 + 2];
#pragma unroll
            for (int m = 0; m < 4; m++) {
                u64 wv = *(const u64*)&Wt[buf][kk][(ty * 4 + m) * 2];
                acc[m][0] = ffma2(wv, h0, acc[m][0]);
                acc[m][1] = ffma2(wv, h1, acc[m][1]);
            }
        }
        if (it < 15) {
            __syncthreads();
            int nb = buf ^ 1;
            float wc[4] = {wr.x, wr.y, wr.z, wr.w};
#pragma unroll
            for (int c = 0; c < 4; c++) {
                Wt[nb][sk + c][sr * 2]     = wc[c];
                Wt[nb][sk + c][sr * 2 + 1] = wc[c];
            }
            *(float4*)&Hs[nb][hk][hc] = hr;
            __syncthreads();
        }
    }

#pragma unroll
    for (int m = 0; m < 4; m++) {
        int i = i0 + ty * 4 + m;
        long base = (long)(b * Lx + i) * Dx + c0 + tx * 4;
        float4 q = *(const float4*)(Q + base);
        float o0, o1, o2, o3;
        unpack2(acc[m][0], o0, o1);
        unpack2(acc[m][1], o2, o3);
        *(float4*)(out + base) = make_float4(
            fmaxf(q.x + o0, 0.f), fmaxf(q.y + o1, 0.f),
            fmaxf(q.z + o2, 0.f), fmaxf(q.w + o3, 0.f));
    }
}

// ---------------------------------------------------------------------------
extern "C" void kernel_launch(void* const* d_in, const int* in_sizes, int n_in,
                              void* d_out, int out_size)
{
    const float* Q   = (const float*)d_in[0];
    const int*   wl  = (const int*)d_in[1];
    const int*   dep = (const int*)d_in[2];
    const float* Wa  = (const float*)d_in[3];
    const float* Wb  = (const float*)d_in[4];
    const float* w2  = (const float*)d_in[5];
    const float* Wd  = (const float*)d_in[6];
    float* out = (float*)d_out;

    float* dst = (out_size >= BLD + Bx + BLL) ? out + BLD : nullptr;

    // projections: A, Bm, H  (384 blocks)
    proj_kernel<<<dim3(32, 4, 3), 256>>>(Q, Wa, Wb, Wd);
    // edge scores + softmax -> g_W (+ tail conversions folded in) (256 blocks)
    edge_kernel<<<dim3(32, Bx), 128>>>(dep, w2, wl, dst);
    // aggregation + residual relu (128 blocks)
    agg_kernel<<<dim3(4, 4, Bx), 256>>>(Q, out);
}

// round 4
// speedup vs baseline: 1.1287x; 1.1287x over previous
#include <cuda_runtime.h>
#include <cuda_bf16.h>

// Problem constants
#define Bx 8
#define Lx 256
#define Dx 256
#define BLD (Bx*Lx*Dx)   // 524288
#define BLL (Bx*Lx*Lx)   // 524288

typedef unsigned long long u64;

// Scratch (device globals — no allocation allowed)
__device__ float g_A[BLD],  g_Bm[BLD],  g_H[BLD];
__device__ float g_A2[BLD], g_Bm2[BLD], g_H2[BLD];   // K-split partials
__device__ float g_W[BLL];                           // softmax weights

// ---- packed f32x2 helpers (Blackwell) --------------------------------------
__device__ __forceinline__ u64 pack2(float lo, float hi) {
    u64 r; asm("mov.b64 %0,{%1,%2};" : "=l"(r) : "f"(lo), "f"(hi)); return r;
}
__device__ __forceinline__ void unpack2(u64 v, float& lo, float& hi) {
    asm("mov.b64 {%0,%1},%2;" : "=f"(lo), "=f"(hi) : "l"(v));
}
__device__ __forceinline__ u64 ffma2(u64 a, u64 b, u64 c) {
    u64 d; asm("fma.rn.f32x2 %0,%1,%2,%3;" : "=l"(d) : "l"(a), "l"(b), "l"(c)); return d;
}
__device__ __forceinline__ u64 fadd2(u64 a, u64 b) {
    u64 d; asm("add.rn.f32x2 %0,%1,%2;" : "=l"(d) : "l"(a), "l"(b)); return d;
}

// ---------------------------------------------------------------------------
// Kernel 1: projections, K-split x2. C[m,n] = sum_k X[m,k]*W[n,k] (NT GEMM)
// BM=128, BN=64, BK=16, 128 threads, 8x8 per thread, f32x2, LDS.128 only.
// grid (16, 4, 6): z>>1 = matrix, z&1 = k-half. 384 blocks.
// X stored DUPLICATED pairs: one LDS.128 = two broadcast f32x2 operands.
// ---------------------------------------------------------------------------
__global__ __launch_bounds__(128) void proj_kernel(
    const float* __restrict__ Q,
    const float* __restrict__ Wa,
    const float* __restrict__ Wb,
    const float* __restrict__ Wd)
{
    int mat = blockIdx.z >> 1;
    int kh  = blockIdx.z & 1;
    const float* W = (mat == 0) ? Wa : (mat == 1) ? Wb : Wd;
    float* Out = (mat == 0) ? (kh ? g_A2 : g_A)
               : (mat == 1) ? (kh ? g_Bm2 : g_Bm)
                            : (kh ? g_H2 : g_H);

    __shared__ __align__(16) float Xs[2][16][268];  // dup pairs [k][2m]
    __shared__ __align__(16) float Ws[2][16][68];   // [k][n]

    int tid = threadIdx.x;
    int m0 = blockIdx.x * 128, n0 = blockIdx.y * 64;
    int ty = tid >> 3;    // 0..15 -> 8 m-rows
    int tx = tid & 7;     // 0..7  -> 8 n-cols
    int sr = tid >> 2;    // 0..31 staging row
    int sk = (tid & 3) * 4;
    int kbase = kh * 128;

    const float* xg = Q + kbase + sk;
    const float* wg = W + kbase + sk;

    float4 xv[4], wv[2];
#pragma unroll
    for (int p = 0; p < 4; p++) xv[p] = *(const float4*)(xg + (m0 + p * 32 + sr) * Dx);
#pragma unroll
    for (int p = 0; p < 2; p++) wv[p] = *(const float4*)(wg + (n0 + p * 32 + sr) * Dx);

    {
#pragma unroll
        for (int p = 0; p < 4; p++) {
            float v[4] = {xv[p].x, xv[p].y, xv[p].z, xv[p].w};
            int r2 = 2 * (p * 32 + sr);
#pragma unroll
            for (int q = 0; q < 4; q++)
                *(u64*)&Xs[0][sk + q][r2] = pack2(v[q], v[q]);
        }
#pragma unroll
        for (int p = 0; p < 2; p++) {
            float v[4] = {wv[p].x, wv[p].y, wv[p].z, wv[p].w};
#pragma unroll
            for (int q = 0; q < 4; q++)
                Ws[0][sk + q][p * 32 + sr] = v[q];
        }
    }
    __syncthreads();

    u64 acc[8][4];
#pragma unroll
    for (int m = 0; m < 8; m++)
#pragma unroll
        for (int n = 0; n < 4; n++) acc[m][n] = 0ull;

#pragma unroll 1
    for (int it = 0; it < 8; it++) {
        int buf = it & 1;
        if (it < 7) {
            int ko = (it + 1) * 16;
#pragma unroll
            for (int p = 0; p < 4; p++) xv[p] = *(const float4*)(xg + (m0 + p * 32 + sr) * Dx + ko);
#pragma unroll
            for (int p = 0; p < 2; p++) wv[p] = *(const float4*)(wg + (n0 + p * 32 + sr) * Dx + ko);
        }
#pragma unroll
        for (int kk = 0; kk < 16; kk++) {
            ulonglong2 wA = *(const ulonglong2*)&Ws[buf][kk][tx * 8];
            ulonglong2 wB = *(const ulonglong2*)&Ws[buf][kk][tx * 8 + 4];
            u64 wq0 = wA.x, wq1 = wA.y, wq2 = wB.x, wq3 = wB.y;
#pragma unroll
            for (int mm = 0; mm < 4; mm++) {
                ulonglong2 xA = *(const ulonglong2*)&Xs[buf][kk][ty * 16 + mm * 4];
                acc[2*mm][0]   = ffma2(xA.x, wq0, acc[2*mm][0]);
                acc[2*mm][1]   = ffma2(xA.x, wq1, acc[2*mm][1]);
                acc[2*mm][2]   = ffma2(xA.x, wq2, acc[2*mm][2]);
                acc[2*mm][3]   = ffma2(xA.x, wq3, acc[2*mm][3]);
                acc[2*mm+1][0] = ffma2(xA.y, wq0, acc[2*mm+1][0]);
                acc[2*mm+1][1] = ffma2(xA.y, wq1, acc[2*mm+1][1]);
                acc[2*mm+1][2] = ffma2(xA.y, wq2, acc[2*mm+1][2]);
                acc[2*mm+1][3] = ffma2(xA.y, wq3, acc[2*mm+1][3]);
            }
        }
        if (it < 7) {
            int nb = buf ^ 1;
#pragma unroll
            for (int p = 0; p < 4; p++) {
                float v[4] = {xv[p].x, xv[p].y, xv[p].z, xv[p].w};
                int r2 = 2 * (p * 32 + sr);
#pragma unroll
                for (int q = 0; q < 4; q++)
                    *(u64*)&Xs[nb][sk + q][r2] = pack2(v[q], v[q]);
            }
#pragma unroll
            for (int p = 0; p < 2; p++) {
                float v[4] = {wv[p].x, wv[p].y, wv[p].z, wv[p].w};
#pragma unroll
                for (int q = 0; q < 4; q++)
                    Ws[nb][sk + q][p * 32 + sr] = v[q];
            }
            __syncthreads();
        }
    }

#pragma unroll
    for (int m = 0; m < 8; m++) {
        int row = m0 + ty * 8 + m;
        float* dst = Out + row * Dx + n0 + tx * 8;
        ulonglong2 o1, o2;
        o1.x = acc[m][0]; o1.y = acc[m][1];
        o2.x = acc[m][2]; o2.y = acc[m][3];
        *(ulonglong2*)(dst)     = o1;
        *(ulonglong2*)(dst + 4) = o2;
    }
}

// ---------------------------------------------------------------------------
// Combine the K-split halves: g_A += g_A2, g_Bm += g_Bm2, g_H += g_H2.
// ---------------------------------------------------------------------------
__global__ __launch_bounds__(256) void combine_kernel()
{
    int idx = blockIdx.x * 256 + threadIdx.x;   // 0 .. BLD/4-1
    int arr = blockIdx.y;
    float4* d; const float4* s;
    if (arr == 0)      { d = (float4*)g_A;  s = (const float4*)g_A2;  }
    else if (arr == 1) { d = (float4*)g_Bm; s = (const float4*)g_Bm2; }
    else               { d = (float4*)g_H;  s = (const float4*)g_H2;  }
    float4 a = d[idx], b = s[idx];
    d[idx] = make_float4(a.x + b.x, a.y + b.y, a.z + b.z, a.w + b.w);
}

// ---------------------------------------------------------------------------
// Kernel 2: edge scores + mask + softmax -> g_W, plus tail conversion.
// Block = (b, 8 rows). 128 threads = 4 warps, 2 rows/warp. Lane jl owns
// j = gp*64 + jl*2 (+0/1). Bt double-buffered per 16-c chunk.
// ---------------------------------------------------------------------------
__device__ __forceinline__ void softmax_row(
    u64 acc[4], int b, int i, int jl,
    const int* __restrict__ dep, float* __restrict__ depout)
{
    const int* dr = dep + (b * Lx + i) * Lx;
    float T[8]; int mk[8];
    float mx = -1e30f;
#pragma unroll
    for (int gp = 0; gp < 4; gp++) {
        int j0 = gp * 64 + jl * 2;
        int2 m2 = *(const int2*)(dr + j0);
        float lo, hi; unpack2(acc[gp], lo, hi);
        mk[2 * gp]     = (m2.x > 0);
        mk[2 * gp + 1] = (m2.y > 0);
        T[2 * gp]     = mk[2 * gp]     ? lo : -100.0f;
        T[2 * gp + 1] = mk[2 * gp + 1] ? hi : -100.0f;
        mx = fmaxf(mx, fmaxf(T[2 * gp], T[2 * gp + 1]));
        if (depout) {
            float2 dv = make_float2((float)m2.x, (float)m2.y);
            *(float2*)(depout + (b * Lx + i) * Lx + j0) = dv;
        }
    }
#pragma unroll
    for (int off = 16; off > 0; off >>= 1)
        mx = fmaxf(mx, __shfl_xor_sync(0xffffffffu, mx, off));

    float E[8], sum = 0.f;
#pragma unroll
    for (int g = 0; g < 8; g++) { E[g] = expf(T[g] - mx); sum += E[g]; }
#pragma unroll
    for (int off = 16; off > 0; off >>= 1)
        sum += __shfl_xor_sync(0xffffffffu, sum, off);

    float inv = 1.0f / sum;
    float* wRow = g_W + (b * Lx + i) * Lx;
#pragma unroll
    for (int gp = 0; gp < 4; gp++) {
        float2 o;
        o.x = mk[2 * gp]     ? E[2 * gp]     * inv : 0.f;
        o.y = mk[2 * gp + 1] ? E[2 * gp + 1] * inv : 0.f;
        *(float2*)(wRow + gp * 64 + jl * 2) = o;
    }
}

__global__ __launch_bounds__(128) void edge_kernel(
    const int* __restrict__ dep,
    const float* __restrict__ w2,
    const int* __restrict__ wl,
    float* __restrict__ dst)   // out + BLD, or nullptr
{
    int b  = blockIdx.y;
    int i0 = blockIdx.x * 8;

    __shared__ __align__(16) float Ash2[8][520];   // duplicated pairs
    __shared__ __align__(16) float w2d[512];       // duplicated pairs
    __shared__ __align__(16) float Bt[2][16][266]; // [cl][j]

    int tid = threadIdx.x;

    // stage 8 A rows, duplicated
#pragma unroll
    for (int p = 0; p < 4; p++) {
        int e = tid * 4 + p * 512;
        int il = e >> 8, c = e & 255;
        float4 v = *(const float4*)(g_A + (b * Lx + i0 + il) * Dx + c);
        *(u64*)&Ash2[il][2 * c]     = pack2(v.x, v.x);
        *(u64*)&Ash2[il][2 * c + 2] = pack2(v.y, v.y);
        *(u64*)&Ash2[il][2 * c + 4] = pack2(v.z, v.z);
        *(u64*)&Ash2[il][2 * c + 6] = pack2(v.w, v.w);
    }
    {
        float a0 = w2[tid];
        float a1 = w2[tid + 128];
        *(u64*)&w2d[2 * tid]         = pack2(a0, a0);
        *(u64*)&w2d[2 * (tid + 128)] = pack2(a1, a1);
    }
    if (dst && blockIdx.x == 0 && blockIdx.y == 0 && tid < Bx)
        dst[tid] = (float)wl[tid];
    float* depout = dst ? dst + Bx : nullptr;

    const float* Bbase = g_Bm + b * Lx * Dx;

    float4 pf[8];
#pragma unroll
    for (int p = 0; p < 8; p++) {
        int e = tid * 4 + p * 512;
        int j = e >> 4, cl = e & 15;
        pf[p] = *(const float4*)(Bbase + j * Dx + cl);
    }
#pragma unroll
    for (int p = 0; p < 8; p++) {
        int e = tid * 4 + p * 512;
        int j = e >> 4, cl = e & 15;
        Bt[0][cl + 0][j] = pf[p].x; Bt[0][cl + 1][j] = pf[p].y;
        Bt[0][cl + 2][j] = pf[p].z; Bt[0][cl + 3][j] = pf[p].w;
    }
    __syncthreads();

    int w  = tid >> 5;   // 0..3
    int jl = tid & 31;
    int r0 = 2 * w, r1 = r0 + 1;

    u64 acc0[4] = {0,0,0,0}, acc1[4] = {0,0,0,0};

#pragma unroll 1
    for (int ch = 0; ch < 16; ch++) {
        int buf = ch & 1;
        if (ch < 15) {
            int c0 = (ch + 1) * 16;
#pragma unroll
            for (int p = 0; p < 8; p++) {
                int e = tid * 4 + p * 512;
                int j = e >> 4, cl = e & 15;
                pf[p] = *(const float4*)(Bbase + j * Dx + c0 + cl);
            }
        }
#pragma unroll
        for (int c2 = 0; c2 < 8; c2++) {
            int cbase = ch * 16 + c2 * 2;
            ulonglong2 A0 = *(const ulonglong2*)&Ash2[r0][cbase * 2];
            ulonglong2 A1 = *(const ulonglong2*)&Ash2[r1][cbase * 2];
            ulonglong2 UU = *(const ulonglong2*)&w2d[cbase * 2];
#pragma unroll
            for (int cc = 0; cc < 2; cc++) {
                u64 a0 = cc ? A0.y : A0.x;
                u64 a1 = cc ? A1.y : A1.x;
                u64 up = cc ? UU.y : UU.x;
                int cl = c2 * 2 + cc;
#pragma unroll
                for (int gp = 0; gp < 4; gp++) {
                    u64 bt = *(const u64*)&Bt[buf][cl][gp * 64 + jl * 2];
                    u64 s0 = fadd2(a0, bt);
                    u64 s1 = fadd2(a1, bt);
                    float x0, y0, x1, y1;
                    unpack2(s0, x0, y0);
                    unpack2(s1, x1, y1);
                    acc0[gp] = ffma2(pack2(fmaxf(x0, 0.f), fmaxf(y0, 0.f)), up, acc0[gp]);
                    acc1[gp] = ffma2(pack2(fmaxf(x1, 0.f), fmaxf(y1, 0.f)), up, acc1[gp]);
                }
            }
        }
        if (ch < 15) {
            int nb = buf ^ 1;
#pragma unroll
            for (int p = 0; p < 8; p++) {
                int e = tid * 4 + p * 512;
                int j = e >> 4, cl = e & 15;
                Bt[nb][cl + 0][j] = pf[p].x; Bt[nb][cl + 1][j] = pf[p].y;
                Bt[nb][cl + 2][j] = pf[p].z; Bt[nb][cl + 3][j] = pf[p].w;
            }
            __syncthreads();
        }
    }

    softmax_row(acc0, b, i0 + r0, jl, dep, depout);
    softmax_row(acc1, b, i0 + r1, jl, dep, depout);
}

// ---------------------------------------------------------------------------
// Kernel 3: agg = w @ H per batch, out = relu(q + agg).  NN GEMM 256x256x256.
// BM=32, BN=64, BK=16, 128 threads, 2x8 per thread, f32x2, double-buffered.
// grid (8, 4, 8) = 256 blocks. W (broadcast operand) stored duplicated.
// ---------------------------------------------------------------------------
__global__ __launch_bounds__(128) void agg_kernel(
    const float* __restrict__ Q,
    float* __restrict__ out)
{
    int b  = blockIdx.z;
    int i0 = blockIdx.x * 32;
    int c0 = blockIdx.y * 64;

    __shared__ __align__(16) float Wt[2][16][76];  // [k][2*i] duplicated
    __shared__ __align__(16) float Hs[2][16][68];  // [k][c]

    int tid = threadIdx.x;
    int ty = tid >> 3;   // 0..15 -> 2 i-rows
    int tx = tid & 7;    // 0..7  -> 8 c-cols

    int sr = tid >> 2;          // 0..31 (W staging row)
    int sk = (tid & 3) * 4;
    int hk = tid >> 4;          // 0..7
    int hc = (tid & 15) * 4;

    const float* Wg = g_W + b * Lx * Lx;
    const float* Hg = g_H + b * Lx * Dx;

    float4 wv, hv[2];
    wv    = *(const float4*)(Wg + (i0 + sr) * Lx + sk);
    hv[0] = *(const float4*)(Hg + hk * Dx + c0 + hc);
    hv[1] = *(const float4*)(Hg + (hk + 8) * Dx + c0 + hc);
    {
        float v[4] = {wv.x, wv.y, wv.z, wv.w};
#pragma unroll
        for (int q = 0; q < 4; q++)
            *(u64*)&Wt[0][sk + q][2 * sr] = pack2(v[q], v[q]);
        *(float4*)&Hs[0][hk][hc]     = hv[0];
        *(float4*)&Hs[0][hk + 8][hc] = hv[1];
    }
    __syncthreads();

    u64 acc[2][4];
#pragma unroll
    for (int m = 0; m < 2; m++)
#pragma unroll
        for (int n = 0; n < 4; n++) acc[m][n] = 0ull;

#pragma unroll 1
    for (int it = 0; it < 16; it++) {
        int buf = it & 1;
        if (it < 15) {
            int ko = (it + 1) * 16;
            wv    = *(const float4*)(Wg + (i0 + sr) * Lx + ko + sk);
            hv[0] = *(const float4*)(Hg + (ko + hk) * Dx + c0 + hc);
            hv[1] = *(const float4*)(Hg + (ko + hk + 8) * Dx + c0 + hc);
        }
#pragma unroll
        for (int kk = 0; kk < 16; kk++) {
            ulonglong2 wp = *(const ulonglong2*)&Wt[buf][kk][ty * 4];
            ulonglong2 hA = *(const ulonglong2*)&Hs[buf][kk][tx * 8];
            ulonglong2 hB = *(const ulonglong2*)&Hs[buf][kk][tx * 8 + 4];
            acc[0][0] = ffma2(wp.x, hA.x, acc[0][0]);
            acc[0][1] = ffma2(wp.x, hA.y, acc[0][1]);
            acc[0][2] = ffma2(wp.x, hB.x, acc[0][2]);
            acc[0][3] = ffma2(wp.x, hB.y, acc[0][3]);
            acc[1][0] = ffma2(wp.y, hA.x, acc[1][0]);
            acc[1][1] = ffma2(wp.y, hA.y, acc[1][1]);
            acc[1][2] = ffma2(wp.y, hB.x, acc[1][2]);
            acc[1][3] = ffma2(wp.y, hB.y, acc[1][3]);
        }
        if (it < 15) {
            int nb = buf ^ 1;
            float v[4] = {wv.x, wv.y, wv.z, wv.w};
#pragma unroll
            for (int q = 0; q < 4; q++)
                *(u64*)&Wt[nb][sk + q][2 * sr] = pack2(v[q], v[q]);
            *(float4*)&Hs[nb][hk][hc]     = hv[0];
            *(float4*)&Hs[nb][hk + 8][hc] = hv[1];
            __syncthreads();
        }
    }

#pragma unroll
    for (int m = 0; m < 2; m++) {
        int i = i0 + ty * 2 + m;
        long base = (long)(b * Lx + i) * Dx + c0 + tx * 8;
        float4 q1 = *(const float4*)(Q + base);
        float4 q2 = *(const float4*)(Q + base + 4);
        float o[8];
#pragma unroll
        for (int n = 0; n < 4; n++) unpack2(acc[m][n], o[2 * n], o[2 * n + 1]);
        *(float4*)(out + base) = make_float4(
            fmaxf(q1.x + o[0], 0.f), fmaxf(q1.y + o[1], 0.f),
            fmaxf(q1.z + o[2], 0.f), fmaxf(q1.w + o[3], 0.f));
        *(float4*)(out + base + 4) = make_float4(
            fmaxf(q2.x + o[4], 0.f), fmaxf(q2.y + o[5], 0.f),
            fmaxf(q2.z + o[6], 0.f), fmaxf(q2.w + o[7], 0.f));
    }
}

// ---------------------------------------------------------------------------
extern "C" void kernel_launch(void* const* d_in, const int* in_sizes, int n_in,
                              void* d_out, int out_size)
{
    const float* Q   = (const float*)d_in[0];
    const int*   wl  = (const int*)d_in[1];
    const int*   dep = (const int*)d_in[2];
    const float* Wa  = (const float*)d_in[3];
    const float* Wb  = (const float*)d_in[4];
    const float* w2  = (const float*)d_in[5];
    const float* Wd  = (const float*)d_in[6];
    float* out = (float*)d_out;

    float* dst = (out_size >= BLD + Bx + BLL) ? out + BLD : nullptr;

    // projections, K-split x2 (384 blocks)
    proj_kernel<<<dim3(16, 4, 6), 128>>>(Q, Wa, Wb, Wd);
    // combine the halves (1536 blocks, tiny)
    combine_kernel<<<dim3(BLD / 4 / 256, 3), 256>>>();
    // edge scores + softmax -> g_W (+ tail conversions) (256 blocks)
    edge_kernel<<<dim3(32, Bx), 128>>>(dep, w2, wl, dst);
    // aggregation + residual relu (256 blocks)
    agg_kernel<<<dim3(8, 4, Bx), 128>>>(Q, out);
}